// round 3
// baseline (speedup 1.0000x reference)
#include <cuda_runtime.h>

// BoxFilter fused separable 9x9 depthwise conv, fp32 NHWC.
// B=4, H=1080, W=1920, C=16 -> out [4, 1072, 1912, 16].
//
// Round-3: horizontal pass was smem-wavefront bound (L1=88.6%). Now 112
// threads each produce 4 consecutive output pixels from a 12-tap sliding
// window: 3 tap-LDS per output instead of 9 (3x cut in the dominant L1
// traffic). Taps streamed (1 live), wx weights register-resident only inside
// the horizontal phase. Vertical pass unchanged: rolling 9-row register
// window, each input element read from HBM exactly once. One barrier / 2 rows
// via double-buffered smem.

namespace {
constexpr int KS       = 9;
constexpr int Hh       = 1080;
constexpr int Ww       = 1920;
constexpr int Cc       = 16;
constexpr int OH       = 1072;        // H - 8
constexpr int OW       = 1912;        // W - 8
constexpr int EXT_PX   = 64;          // strip width incl. horizontal halo
constexpr int OUT_PX   = 56;          // output pixels per strip
constexpr int NTH      = EXT_PX * 4;  // 256 threads (4 float4-quads per pixel)
constexpr int GRID_X   = 35;          // ceil(1912/56), last tile overlapped
constexpr int GRID_Y   = 8;
constexpr int ROWS_PB  = OH / GRID_Y;       // 134 output rows per block
constexpr int ITERS    = ROWS_PB / 2;       // 67 two-row iterations
constexpr int IN_ROWS  = ROWS_PB + 8;       // 142 input rows touched
constexpr int IN_ROW_U2  = Ww * Cc / 4;     // 7680 ulonglong2 per input row
constexpr int OUT_ROW_U2 = OW * Cc / 4;     // 7648 ulonglong2 per output row
// horizontal phase: 2 rows * 14 groups * 4 quads = 112 threads, 4 px each
constexpr int HTH      = 112;
}

typedef unsigned long long u64;

// packed 2xfp32 fma: d = a*b + d
__device__ __forceinline__ void fma2(u64 &d, const u64 a, const u64 b) {
    asm("fma.rn.f32x2 %0, %1, %2, %0;" : "+l"(d) : "l"(a), "l"(b));
}

__global__ void __launch_bounds__(NTH, 3)
box_kernel(const float* __restrict__ xg, const float* __restrict__ wyg,
           const float* __restrict__ wxg, float* __restrict__ og)
{
    __shared__ ulonglong2 wy_s[KS * 4];      // [tap][quad]
    __shared__ ulonglong2 wx_s[KS * 4];
    __shared__ ulonglong2 sb[2][2][NTH];     // [buf][row-of-pair][px*4+q]

    const int tid = threadIdx.x;
    const int q   = tid & 3;        // which float4 of the 16 channels
    const int pl  = tid >> 2;       // pixel within strip, 0..63

    const int bx = blockIdx.x, by = blockIdx.y, b = blockIdx.z;
    // Overlap the last tile so no access is ever out of bounds in x.
    const int px0 = min(bx * OUT_PX, OW - OUT_PX);
    const int r0  = by * ROWS_PB;

    // Stage weights in smem (layout [k*4 + q], matching global).
    const ulonglong2* wyv = reinterpret_cast<const ulonglong2*>(wyg);
    const ulonglong2* wxv = reinterpret_cast<const ulonglong2*>(wxg);
    if (tid < KS * 4)                    wy_s[tid]      = wyv[tid];
    else if (tid >= 64 && tid < 64 + 36) wx_s[tid - 64] = wxv[tid - 64];

    const ulonglong2* ip = reinterpret_cast<const ulonglong2*>(xg)
        + (size_t)(b * Hh + r0) * IN_ROW_U2 + (px0 + pl) * 4 + q;

    // Horizontal-phase mapping (threads 0..111): 4 consecutive px per thread.
    const bool hact = (tid < HTH);
    const int  q2   = tid & 3;
    const int  rest = tid >> 2;          // 0..27 when active
    const int  row2 = (rest >= 14) ? 1 : 0;
    const int  px   = (rest - row2 * 14) * 4;   // 0,4,...,52

    // Per-block output base for row pair 0; advances 2 rows per iteration.
    ulonglong2* ob = reinterpret_cast<ulonglong2*>(og)
        + (size_t)(b * OH + r0) * OUT_ROW_U2 + px0 * 4;

    // Prime rolling window with input rows 0..7; cur = row 8, nxt = row 9.
    ulonglong2 win[8], cur, nxt;
    #pragma unroll
    for (int k = 0; k < 8; ++k) { win[k] = *ip; ip += IN_ROW_U2; }
    cur = *ip; ip += IN_ROW_U2;
    nxt = *ip; ip += IN_ROW_U2;

    __syncthreads();   // weights visible

    for (int i = 0; i < ITERS; ++i) {
        // Prefetch input rows 2i+10, 2i+11 (consumed next iteration).
        ulonglong2 p0 = cur, p1 = cur;
        if (2 * i + 10 < IN_ROWS) p0 = ip[0];
        if (2 * i + 11 < IN_ROWS) p1 = ip[IN_ROW_U2];
        ip += 2 * IN_ROW_U2;

        // Vertical 9-tap for output rows 2i and 2i+1 from register window.
        u64 a0x = 0, a0y = 0, a1x = 0, a1y = 0;
        #pragma unroll
        for (int k = 0; k < KS; ++k) {
            const ulonglong2 w   = wy_s[k * 4 + q];
            const ulonglong2 r0v = (k < 8) ? win[k] : cur;
            const ulonglong2 r1v = (k < 7) ? win[k + 1] : ((k == 7) ? cur : nxt);
            fma2(a0x, w.x, r0v.x); fma2(a0y, w.y, r0v.y);
            fma2(a1x, w.x, r1v.x); fma2(a1y, w.y, r1v.y);
        }

        const int buf = i & 1;
        { ulonglong2 v; v.x = a0x; v.y = a0y; sb[buf][0][tid] = v; }
        { ulonglong2 v; v.x = a1x; v.y = a1y; sb[buf][1][tid] = v; }
        __syncthreads();

        // Horizontal 9-tap, 4 outputs per active thread, 12-tap sliding window.
        if (hact) {
            // wx weights register-resident for this phase only.
            ulonglong2 w[KS];
            #pragma unroll
            for (int k = 0; k < KS; ++k) w[k] = wx_s[k * 4 + q2];

            const ulonglong2* s = &sb[buf][row2][px * 4 + q2];
            u64 ax[4] = {0, 0, 0, 0}, ay[4] = {0, 0, 0, 0};
            #pragma unroll
            for (int j = 0; j < 12; ++j) {
                const ulonglong2 t = s[4 * j];
                #pragma unroll
                for (int o = 0; o < 4; ++o) {
                    const int k = j - o;
                    if (k >= 0 && k < KS) {
                        fma2(ax[o], w[k].x, t.x);
                        fma2(ay[o], w[k].y, t.y);
                    }
                }
            }
            ulonglong2* o2 = ob + (size_t)row2 * OUT_ROW_U2 + px * 4 + q2;
            #pragma unroll
            for (int o = 0; o < 4; ++o) {
                ulonglong2 v; v.x = ax[o]; v.y = ay[o];
                o2[o * 4] = v;
            }
        }
        ob += 2 * OUT_ROW_U2;

        // Slide the vertical window down two rows.
        #pragma unroll
        for (int k = 0; k < 6; ++k) win[k] = win[k + 2];
        win[6] = cur; win[7] = nxt;
        cur = p0; nxt = p1;
    }
}

extern "C" void kernel_launch(void* const* d_in, const int* in_sizes, int n_in,
                              void* d_out, int out_size)
{
    const float* x  = (const float*)d_in[0];
    const float* wy = (const float*)d_in[1];
    const float* wx = (const float*)d_in[2];
    float* out = (float*)d_out;

    dim3 grid(GRID_X, GRID_Y, 4);
    dim3 block(NTH);
    box_kernel<<<grid, block>>>(x, wy, wx, out);
}

// round 4
// speedup vs baseline: 1.4426x; 1.4426x over previous
#include <cuda_runtime.h>

// BoxFilter fused separable 9x9 depthwise conv, fp32 NHWC.
// B=4, H=1080, W=1920, C=16 -> out [4, 1072, 1912, 16].
//
// Round-4: R2/R3 were instruction/issue + smem-crossbar limited (~2200
// warp-inst per 2-row iter, issue 30%, L1 87%). When all 9 taps of a kernel
// are bitwise-equal (verified at runtime with a block-wide vote), the filter
// is weight * running-sum:
//   vertical:   S <- S + new_row - old_row        (2 packed ops/row)
//   horizontal: sliding 9-window sum over 4 outputs per thread
//   final:      out = (wy0*wx0) * sum
// Non-uniform weights fall back to the full 9-tap FMA path (correct for any
// input). Padded smem layout (4 extra slots per 4 px) makes tap loads and
// stores bank-conflict-free. One barrier per 2 rows, double buffered.

namespace {
constexpr int KS       = 9;
constexpr int Hh       = 1080;
constexpr int Ww       = 1920;
constexpr int Cc       = 16;
constexpr int OH       = 1072;        // H - 8
constexpr int OW       = 1912;        // W - 8
constexpr int EXT_PX   = 64;          // strip width incl. horizontal halo
constexpr int OUT_PX   = 56;          // output pixels per strip
constexpr int NTH      = EXT_PX * 4;  // 256 threads (4 float4-quads per pixel)
constexpr int GRID_X   = 35;          // ceil(1912/56), last tile overlapped
constexpr int GRID_Y   = 8;
constexpr int ROWS_PB  = OH / GRID_Y;       // 134 output rows per block
constexpr int ITERS    = ROWS_PB / 2;       // 67 two-row iterations
constexpr int IN_ROWS  = ROWS_PB + 8;       // 142 input rows touched
constexpr int IN_ROW_U2  = Ww * Cc / 4;     // 7680 ulonglong2 per input row
constexpr int OUT_ROW_U2 = OW * Cc / 4;     // 7648 ulonglong2 per output row
constexpr int HTH      = 112;   // horizontal threads: 2 rows * 14 grp * 4 q
constexpr int SBN      = 320;   // padded row buffer entries (max idx 315)
}

typedef unsigned long long u64;

__device__ __forceinline__ void fma2(u64 &d, const u64 a, const u64 b) {
    asm("fma.rn.f32x2 %0, %1, %2, %0;" : "+l"(d) : "l"(a), "l"(b));
}
__device__ __forceinline__ void add2(u64 &d, const u64 a) {
    asm("add.rn.f32x2 %0, %0, %1;" : "+l"(d) : "l"(a));
}
__device__ __forceinline__ u64 mul2(const u64 a, const u64 b) {
    u64 r; asm("mul.rn.f32x2 %0, %1, %2;" : "=l"(r) : "l"(a), "l"(b));
    return r;
}
// packed (-1.0f, -1.0f): d -= v  via  d = v*(-1) + d
#define NEG1 0xBF800000BF800000ull
__device__ __forceinline__ void sub2(u64 &d, const u64 v) { fma2(d, NEG1, v); }

// padded smem index for pixel p, quad qq: conflict-free tap reads
__device__ __forceinline__ int sidx(int p, int qq) {
    return p * 4 + qq + ((p >> 2) << 2);
}

__global__ void __launch_bounds__(NTH, 3)
box_kernel(const float* __restrict__ xg, const float* __restrict__ wyg,
           const float* __restrict__ wxg, float* __restrict__ og)
{
    __shared__ ulonglong2 wy_s[KS * 4];      // [tap][quad]
    __shared__ ulonglong2 wx_s[KS * 4];
    __shared__ ulonglong2 sb[2][2][SBN];     // [buf][row-of-pair][padded col]

    const int tid = threadIdx.x;
    const int q   = tid & 3;        // which float4 of the 16 channels
    const int pl  = tid >> 2;       // pixel within strip, 0..63

    const int bx = blockIdx.x, by = blockIdx.y, b = blockIdx.z;
    const int px0 = min(bx * OUT_PX, OW - OUT_PX);   // overlapped last tile
    const int r0  = by * ROWS_PB;

    const ulonglong2* wyv = reinterpret_cast<const ulonglong2*>(wyg);
    const ulonglong2* wxv = reinterpret_cast<const ulonglong2*>(wxg);
    if (tid < KS * 4)                    wy_s[tid]      = wyv[tid];
    else if (tid >= 64 && tid < 64 + 36) wx_s[tid - 64] = wxv[tid - 64];
    __syncthreads();

    // Block-wide uniformity vote (bitwise) for this thread's channel quad.
    int myuni = 1;
    {
        const ulonglong2 y0 = wy_s[q], x0 = wx_s[q];
        #pragma unroll
        for (int k = 1; k < KS; ++k) {
            const ulonglong2 yk = wy_s[k * 4 + q], xk = wx_s[k * 4 + q];
            myuni &= (yk.x == y0.x) & (yk.y == y0.y)
                   & (xk.x == x0.x) & (xk.y == x0.y);
        }
    }
    const int uniform = __syncthreads_and(myuni);

    const ulonglong2* ip = reinterpret_cast<const ulonglong2*>(xg)
        + (size_t)(b * Hh + r0) * IN_ROW_U2 + (px0 + pl) * 4 + q;

    const int sst = sidx(pl, q);    // padded store slot for this thread

    // Prime rolling window: rows 0..7 in win, cur = row 8, nxt = row 9.
    ulonglong2 win[8], cur, nxt;
    #pragma unroll
    for (int k = 0; k < 8; ++k) { win[k] = *ip; ip += IN_ROW_U2; }
    cur = *ip; ip += IN_ROW_U2;
    nxt = *ip; ip += IN_ROW_U2;

    if (uniform) {
        // ---------- fast path: running sums ----------
        // Horizontal-phase mapping: 112 threads, 4 consecutive px each.
        const bool hact = (tid < HTH);
        const int  rest = tid >> 2;               // 0..27 when active
        const int  row2 = (rest >= 14) ? 1 : 0;
        const int  px   = (rest - row2 * 14) * 4; // 0,4,...,52
        const int  hbase = px * 5 + q;            // sidx(px+j,q) = hbase + off(j)

        // combined scale = wy0 * wx0 (componentwise, packed)
        ulonglong2 scale;
        scale.x = mul2(wy_s[q].x, wx_s[q].x);
        scale.y = mul2(wy_s[q].y, wx_s[q].y);

        ulonglong2* ob = reinterpret_cast<ulonglong2*>(og)
            + (size_t)(b * OH + r0) * OUT_ROW_U2 + px0 * 4;

        // S = sum of rows 0..8 (win[0..7] + cur)
        u64 Sx = cur.x, Sy = cur.y;
        #pragma unroll
        for (int k = 0; k < 8; ++k) { add2(Sx, win[k].x); add2(Sy, win[k].y); }

        for (int i = 0; i < ITERS; ++i) {
            ulonglong2 p0 = cur, p1 = cur;
            if (2 * i + 10 < IN_ROWS) p0 = ip[0];
            if (2 * i + 11 < IN_ROWS) p1 = ip[IN_ROW_U2];
            ip += 2 * IN_ROW_U2;

            // row 2i sum = S; row 2i+1 sum = S + nxt - win[0]
            u64 S1x = Sx, S1y = Sy;
            add2(S1x, nxt.x); sub2(S1x, win[0].x);
            add2(S1y, nxt.y); sub2(S1y, win[0].y);

            const int buf = i & 1;
            { ulonglong2 v; v.x = Sx;  v.y = Sy;  sb[buf][0][sst] = v; }
            { ulonglong2 v; v.x = S1x; v.y = S1y; sb[buf][1][sst] = v; }

            // advance S to row 2i+2: S1 + p0 - win[1]
            Sx = S1x; add2(Sx, p0.x); sub2(Sx, win[1].x);
            Sy = S1y; add2(Sy, p0.y); sub2(Sy, win[1].y);

            // slide window by 2
            #pragma unroll
            for (int k = 0; k < 6; ++k) win[k] = win[k + 2];
            win[6] = cur; win[7] = nxt;
            cur = p0; nxt = p1;

            __syncthreads();

            if (hact) {
                const ulonglong2* s = sb[buf][row2];
                // tap offsets j=0..11: j*4 + ((j>>2)<<2) (compile-time)
                ulonglong2 t[12];
                #pragma unroll
                for (int j = 0; j < 12; ++j)
                    t[j] = s[hbase + j * 4 + ((j >> 2) << 2)];

                u64 sx = t[0].x, sy = t[0].y;
                #pragma unroll
                for (int j = 1; j < 9; ++j) { add2(sx, t[j].x); add2(sy, t[j].y); }

                ulonglong2* o2 = ob + (size_t)row2 * OUT_ROW_U2 + px * 4 + q;
                #pragma unroll
                for (int o = 0; o < 4; ++o) {
                    ulonglong2 v;
                    v.x = mul2(scale.x, sx);
                    v.y = mul2(scale.y, sy);
                    o2[o * 4] = v;
                    if (o < 3) {
                        add2(sx, t[o + 9].x); sub2(sx, t[o].x);
                        add2(sy, t[o + 9].y); sub2(sy, t[o].y);
                    }
                }
            }
            ob += 2 * OUT_ROW_U2;
            __syncthreads();   // protect sb reuse (buf toggles every iter)
        }
    } else {
        // ---------- fallback: full 9-tap FMA (any weights) ----------
        const bool emit = (pl < OUT_PX);
        ulonglong2* op = reinterpret_cast<ulonglong2*>(og)
            + (size_t)(b * OH + r0) * OUT_ROW_U2 + (px0 + pl) * 4 + q;

        for (int i = 0; i < ITERS; ++i) {
            ulonglong2 p0 = cur, p1 = cur;
            if (2 * i + 10 < IN_ROWS) p0 = ip[0];
            if (2 * i + 11 < IN_ROWS) p1 = ip[IN_ROW_U2];
            ip += 2 * IN_ROW_U2;

            u64 a0x = 0, a0y = 0, a1x = 0, a1y = 0;
            #pragma unroll
            for (int k = 0; k < KS; ++k) {
                const ulonglong2 w   = wy_s[k * 4 + q];
                const ulonglong2 r0v = (k < 8) ? win[k] : cur;
                const ulonglong2 r1v = (k < 7) ? win[k + 1] : ((k == 7) ? cur : nxt);
                fma2(a0x, w.x, r0v.x); fma2(a0y, w.y, r0v.y);
                fma2(a1x, w.x, r1v.x); fma2(a1y, w.y, r1v.y);
            }
            const int buf = i & 1;
            { ulonglong2 v; v.x = a0x; v.y = a0y; sb[buf][0][sst] = v; }
            { ulonglong2 v; v.x = a1x; v.y = a1y; sb[buf][1][sst] = v; }

            #pragma unroll
            for (int k = 0; k < 6; ++k) win[k] = win[k + 2];
            win[6] = cur; win[7] = nxt;
            cur = p0; nxt = p1;

            __syncthreads();

            if (emit) {
                u64 o0x = 0, o0y = 0, o1x = 0, o1y = 0;
                #pragma unroll
                for (int j = 0; j < KS; ++j) {
                    const ulonglong2 w  = wx_s[j * 4 + q];
                    const ulonglong2 t0 = sb[buf][0][sidx(pl + j, q)];
                    const ulonglong2 t1 = sb[buf][1][sidx(pl + j, q)];
                    fma2(o0x, w.x, t0.x); fma2(o0y, w.y, t0.y);
                    fma2(o1x, w.x, t1.x); fma2(o1y, w.y, t1.y);
                }
                ulonglong2 v0; v0.x = o0x; v0.y = o0y;
                ulonglong2 v1; v1.x = o1x; v1.y = o1y;
                op[0]          = v0;
                op[OUT_ROW_U2] = v1;
            }
            op += 2 * OUT_ROW_U2;
            __syncthreads();
        }
    }
}

extern "C" void kernel_launch(void* const* d_in, const int* in_sizes, int n_in,
                              void* d_out, int out_size)
{
    const float* x  = (const float*)d_in[0];
    const float* wy = (const float*)d_in[1];
    const float* wx = (const float*)d_in[2];
    float* out = (float*)d_out;

    dim3 grid(GRID_X, GRID_Y, 4);
    dim3 block(NTH);
    box_kernel<<<grid, block>>>(x, wy, wx, out);
}

// round 5
// speedup vs baseline: 1.7237x; 1.1948x over previous
#include <cuda_runtime.h>

// BoxFilter fused separable 9x9 depthwise conv, fp32 NHWC.
// B=4, H=1080, W=1920, C=16 -> out [4, 1072, 1912, 16].
//
// Round-5: R4 was latency-exposed (nothing saturated: DRAM 52%, L1 47%,
// issue 20%, occ 33%). Changes:
//  * rolling 9-row register window replaced by L2 reload of the leaving rows
//    (reuse distance 9 rows ~ 16MB chip-wide, lives in the 126MB L2)
//    -> regs drop ~80 -> ~60 -> __launch_bounds__(256,4) = 32 warps/SM
//  * software pipeline: loads for iter i issued first, horizontal phase of
//    iter i-1 runs in between (hides L2/DRAM latency), then S-advance+stores
//  * ONE __syncthreads per 2-row iteration (double-buffer proof: reads of a
//    buffer finish before that thread reaches the next barrier; re-writes
//    happen after it)
//  * streaming stores for the output, evict-first loads for leaving rows

namespace {
constexpr int KS       = 9;
constexpr int Hh       = 1080;
constexpr int Ww       = 1920;
constexpr int Cc       = 16;
constexpr int OH       = 1072;        // H - 8
constexpr int OW       = 1912;        // W - 8
constexpr int EXT_PX   = 64;          // strip width incl. horizontal halo
constexpr int OUT_PX   = 56;          // output pixels per strip
constexpr int NTH      = EXT_PX * 4;  // 256 threads
constexpr int GRID_X   = 35;          // ceil(1912/56), last tile overlapped
constexpr int GRID_Y   = 8;
constexpr int ROWS_PB  = OH / GRID_Y;       // 134 output rows per block
constexpr int ITERS    = ROWS_PB / 2;       // 67 two-row iterations
constexpr int IN_ROWS  = ROWS_PB + 8;       // 142 input rows touched
constexpr int IN_ROW_U2  = Ww * Cc / 4;     // 7680 ulonglong2 per input row
constexpr int OUT_ROW_U2 = OW * Cc / 4;     // 7648 ulonglong2 per output row
constexpr int HTH      = 112;   // horizontal threads: 2 rows * 14 grp * 4 q
constexpr int SBN      = 320;   // padded row buffer entries
}

typedef unsigned long long u64;

__device__ __forceinline__ void fma2(u64 &d, const u64 a, const u64 b) {
    asm("fma.rn.f32x2 %0, %1, %2, %0;" : "+l"(d) : "l"(a), "l"(b));
}
__device__ __forceinline__ void add2(u64 &d, const u64 a) {
    asm("add.rn.f32x2 %0, %0, %1;" : "+l"(d) : "l"(a));
}
__device__ __forceinline__ u64 mul2(const u64 a, const u64 b) {
    u64 r; asm("mul.rn.f32x2 %0, %1, %2;" : "=l"(r) : "l"(a), "l"(b));
    return r;
}
#define NEG1 0xBF800000BF800000ull
__device__ __forceinline__ void sub2(u64 &d, const u64 v) { fma2(d, NEG1, v); }

// 128-bit global load/store helpers
__device__ __forceinline__ ulonglong2 ldg2(const ulonglong2* p) {
    ulonglong2 v;
    asm volatile("ld.global.v2.u64 {%0,%1}, [%2];"
                 : "=l"(v.x), "=l"(v.y) : "l"(p));
    return v;
}
__device__ __forceinline__ ulonglong2 ldcs2(const ulonglong2* p) {
    ulonglong2 v;
    asm volatile("ld.global.cs.v2.u64 {%0,%1}, [%2];"
                 : "=l"(v.x), "=l"(v.y) : "l"(p));
    return v;
}
__device__ __forceinline__ void stcs2(ulonglong2* p, const u64 a, const u64 b) {
    asm volatile("st.global.cs.v2.u64 [%0], {%1,%2};" :: "l"(p), "l"(a), "l"(b));
}

// padded smem index for pixel p, quad qq (conflict-free per 8-lane phase)
__device__ __forceinline__ int sidx(int p, int qq) {
    return p * 4 + qq + ((p >> 2) << 2);
}

__global__ void __launch_bounds__(NTH, 4)
box_kernel(const float* __restrict__ xg, const float* __restrict__ wyg,
           const float* __restrict__ wxg, float* __restrict__ og)
{
    __shared__ ulonglong2 wy_s[KS * 4];
    __shared__ ulonglong2 wx_s[KS * 4];
    __shared__ ulonglong2 sb[2][2][SBN];     // [buf][row-of-pair][padded col]

    const int tid = threadIdx.x;
    const int q   = tid & 3;
    const int pl  = tid >> 2;

    const int bx = blockIdx.x, by = blockIdx.y, b = blockIdx.z;
    const int px0 = min(bx * OUT_PX, OW - OUT_PX);
    const int r0  = by * ROWS_PB;

    const ulonglong2* wyv = reinterpret_cast<const ulonglong2*>(wyg);
    const ulonglong2* wxv = reinterpret_cast<const ulonglong2*>(wxg);
    if (tid < KS * 4)                    wy_s[tid]      = wyv[tid];
    else if (tid >= 64 && tid < 64 + 36) wx_s[tid - 64] = wxv[tid - 64];
    __syncthreads();

    // Block-wide bitwise uniformity vote for this thread's channel quad.
    int myuni = 1;
    {
        const ulonglong2 y0 = wy_s[q], x0 = wx_s[q];
        #pragma unroll
        for (int k = 1; k < KS; ++k) {
            const ulonglong2 yk = wy_s[k * 4 + q], xk = wx_s[k * 4 + q];
            myuni &= (yk.x == y0.x) & (yk.y == y0.y)
                   & (xk.x == x0.x) & (xk.y == x0.y);
        }
    }
    const int uniform = __syncthreads_and(myuni);

    const ulonglong2* ib = reinterpret_cast<const ulonglong2*>(xg)
        + (size_t)(b * Hh + r0) * IN_ROW_U2 + (px0 + pl) * 4 + q;
    const int sst = sidx(pl, q);

    if (uniform) {
        // ------------- fast path: running sums, pipelined -------------
        const bool hact = (tid < HTH);
        const int  rest = tid >> 2;               // 0..27 when active
        const int  row2 = (rest >= 14) ? 1 : 0;
        const int  px   = (rest - row2 * 14) * 4; // 0,4,...,52
        const int  hbase = px * 5 + q;

        ulonglong2 scale;
        scale.x = mul2(wy_s[q].x, wx_s[q].x);
        scale.y = mul2(wy_s[q].y, wx_s[q].y);

        ulonglong2* ob = reinterpret_cast<ulonglong2*>(og)
            + (size_t)(b * OH + r0) * OUT_ROW_U2 + px0 * 4
            + (size_t)row2 * OUT_ROW_U2 + px * 4 + q;

        // Prologue: S = sum rows 0..8; keep rows 0,1 as first leaving rows.
        u64 Sx, Sy;
        ulonglong2 o0, o1;
        {
            ulonglong2 v = ldg2(ib);
            Sx = v.x; Sy = v.y; o0 = v;
            #pragma unroll
            for (int k = 1; k < 9; ++k) {
                v = ldg2(ib + k * IN_ROW_U2);
                add2(Sx, v.x); add2(Sy, v.y);
                if (k == 1) o1 = v;
            }
        }
        ulonglong2 n0 = ldg2(ib +  9 * IN_ROW_U2);
        ulonglong2 n1 = ldg2(ib + 10 * IN_ROW_U2);

        // iter 0 vertical: rows 0,1
        {
            u64 S1x = Sx, S1y = Sy;
            add2(S1x, n0.x); sub2(S1x, o0.x);
            add2(S1y, n0.y); sub2(S1y, o0.y);
            { ulonglong2 v; v.x = Sx;  v.y = Sy;  sb[0][0][sst] = v; }
            { ulonglong2 v; v.x = S1x; v.y = S1y; sb[0][1][sst] = v; }
            // S <- rows 2..10
            add2(S1x, n1.x); sub2(S1x, o1.x);
            add2(S1y, n1.y); sub2(S1y, o1.y);
            Sx = S1x; Sy = S1y;
        }
        __syncthreads();

        for (int i = 1; i < ITERS; ++i) {
            // 1) issue loads for iter i (consumed after the horizontal phase)
            const int nr1 = min(2 * i + 10, IN_ROWS - 1);
            ulonglong2 Lo0 = ldcs2(ib + (2 * i)     * IN_ROW_U2);
            ulonglong2 Lo1 = ldcs2(ib + (2 * i + 1) * IN_ROW_U2);
            ulonglong2 Ln0 = ldg2 (ib + (2 * i + 9) * IN_ROW_U2);
            ulonglong2 Ln1 = ldg2 (ib + nr1         * IN_ROW_U2);

            // 2) horizontal phase for iter i-1 (covers the load latency)
            if (hact) {
                const ulonglong2* s = sb[(i - 1) & 1][row2];
                u64 ax0 = 0, ax1 = 0, ax2 = 0, ax3 = 0;
                u64 ay0 = 0, ay1 = 0, ay2 = 0, ay3 = 0;
                #pragma unroll
                for (int j = 0; j < 12; ++j) {
                    const ulonglong2 t = s[hbase + j * 4 + ((j >> 2) << 2)];
                    if (j < 9)           { add2(ax0, t.x); add2(ay0, t.y); }
                    if (j >= 1 && j < 10){ add2(ax1, t.x); add2(ay1, t.y); }
                    if (j >= 2 && j < 11){ add2(ax2, t.x); add2(ay2, t.y); }
                    if (j >= 3)          { add2(ax3, t.x); add2(ay3, t.y); }
                }
                stcs2(ob + 0 * 4, mul2(scale.x, ax0), mul2(scale.y, ay0));
                stcs2(ob + 1 * 4, mul2(scale.x, ax1), mul2(scale.y, ay1));
                stcs2(ob + 2 * 4, mul2(scale.x, ax2), mul2(scale.y, ay2));
                stcs2(ob + 3 * 4, mul2(scale.x, ax3), mul2(scale.y, ay3));
            }
            ob += 2 * OUT_ROW_U2;

            // 3) vertical advance for iter i: rows 2i, 2i+1
            u64 S1x = Sx, S1y = Sy;
            add2(S1x, Ln0.x); sub2(S1x, Lo0.x);
            add2(S1y, Ln0.y); sub2(S1y, Lo0.y);
            { ulonglong2 v; v.x = Sx;  v.y = Sy;  sb[i & 1][0][sst] = v; }
            { ulonglong2 v; v.x = S1x; v.y = S1y; sb[i & 1][1][sst] = v; }
            add2(S1x, Ln1.x); sub2(S1x, Lo1.x);
            add2(S1y, Ln1.y); sub2(S1y, Lo1.y);
            Sx = S1x; Sy = S1y;

            __syncthreads();
        }

        // Epilogue: horizontal phase for the last iteration.
        if (hact) {
            const ulonglong2* s = sb[(ITERS - 1) & 1][row2];
            u64 ax0 = 0, ax1 = 0, ax2 = 0, ax3 = 0;
            u64 ay0 = 0, ay1 = 0, ay2 = 0, ay3 = 0;
            #pragma unroll
            for (int j = 0; j < 12; ++j) {
                const ulonglong2 t = s[hbase + j * 4 + ((j >> 2) << 2)];
                if (j < 9)           { add2(ax0, t.x); add2(ay0, t.y); }
                if (j >= 1 && j < 10){ add2(ax1, t.x); add2(ay1, t.y); }
                if (j >= 2 && j < 11){ add2(ax2, t.x); add2(ay2, t.y); }
                if (j >= 3)          { add2(ax3, t.x); add2(ay3, t.y); }
            }
            stcs2(ob + 0 * 4, mul2(scale.x, ax0), mul2(scale.y, ay0));
            stcs2(ob + 1 * 4, mul2(scale.x, ax1), mul2(scale.y, ay1));
            stcs2(ob + 2 * 4, mul2(scale.x, ax2), mul2(scale.y, ay2));
            stcs2(ob + 3 * 4, mul2(scale.x, ax3), mul2(scale.y, ay3));
        }
    } else {
        // ------------- fallback: full 9-tap FMA (any weights) -------------
        const bool emit = (pl < OUT_PX);
        ulonglong2* op = reinterpret_cast<ulonglong2*>(og)
            + (size_t)(b * OH + r0) * OUT_ROW_U2 + (px0 + pl) * 4 + q;

        ulonglong2 win[8], cur, nxt;
        const ulonglong2* ip = ib;
        #pragma unroll
        for (int k = 0; k < 8; ++k) { win[k] = *ip; ip += IN_ROW_U2; }
        cur = *ip; ip += IN_ROW_U2;
        nxt = *ip; ip += IN_ROW_U2;

        for (int i = 0; i < ITERS; ++i) {
            ulonglong2 p0 = cur, p1 = cur;
            if (2 * i + 10 < IN_ROWS) p0 = ip[0];
            if (2 * i + 11 < IN_ROWS) p1 = ip[IN_ROW_U2];
            ip += 2 * IN_ROW_U2;

            u64 a0x = 0, a0y = 0, a1x = 0, a1y = 0;
            #pragma unroll
            for (int k = 0; k < KS; ++k) {
                const ulonglong2 w   = wy_s[k * 4 + q];
                const ulonglong2 r0v = (k < 8) ? win[k] : cur;
                const ulonglong2 r1v = (k < 7) ? win[k + 1] : ((k == 7) ? cur : nxt);
                fma2(a0x, w.x, r0v.x); fma2(a0y, w.y, r0v.y);
                fma2(a1x, w.x, r1v.x); fma2(a1y, w.y, r1v.y);
            }
            const int buf = i & 1;
            { ulonglong2 v; v.x = a0x; v.y = a0y; sb[buf][0][sst] = v; }
            { ulonglong2 v; v.x = a1x; v.y = a1y; sb[buf][1][sst] = v; }

            #pragma unroll
            for (int k = 0; k < 6; ++k) win[k] = win[k + 2];
            win[6] = cur; win[7] = nxt;
            cur = p0; nxt = p1;

            __syncthreads();

            if (emit) {
                u64 o0x = 0, o0y = 0, o1x = 0, o1y = 0;
                #pragma unroll
                for (int j = 0; j < KS; ++j) {
                    const ulonglong2 w  = wx_s[j * 4 + q];
                    const ulonglong2 t0 = sb[buf][0][sidx(pl + j, q)];
                    const ulonglong2 t1 = sb[buf][1][sidx(pl + j, q)];
                    fma2(o0x, w.x, t0.x); fma2(o0y, w.y, t0.y);
                    fma2(o1x, w.x, t1.x); fma2(o1y, w.y, t1.y);
                }
                ulonglong2 v0; v0.x = o0x; v0.y = o0y;
                ulonglong2 v1; v1.x = o1x; v1.y = o1y;
                op[0]          = v0;
                op[OUT_ROW_U2] = v1;
            }
            op += 2 * OUT_ROW_U2;
            __syncthreads();
        }
    }
}

extern "C" void kernel_launch(void* const* d_in, const int* in_sizes, int n_in,
                              void* d_out, int out_size)
{
    const float* x  = (const float*)d_in[0];
    const float* wy = (const float*)d_in[1];
    const float* wx = (const float*)d_in[2];
    float* out = (float*)d_out;

    dim3 grid(GRID_X, GRID_Y, 4);
    dim3 block(NTH);
    box_kernel<<<grid, block>>>(x, wy, wx, out);
}

// round 6
// speedup vs baseline: 1.8543x; 1.0758x over previous
#include <cuda_runtime.h>

// BoxFilter fused separable 9x9 depthwise conv, fp32 NHWC.
// B=4, H=1080, W=1920, C=16 -> out [4, 1072, 1912, 16].
//
// Round-6: R5 moved exactly the ideal 1.03GB over HBM but only reached 63% of
// peak BW (latency-exposed: issue 24%, 67 barriers/block, horizontal phase on
// 44% of threads). Changes:
//  * 4 output rows per iteration: 8 LDG.128 in flight per thread (2x MLP),
//    one barrier per 4 rows, horizontal phase on 208/240 threads (87%)
//  * re-tiled to OUT_PX=52 / 240 threads / grid (37,4,4) = 592 blocks
//    = exactly 148 SMs x 4 resident blocks: single perfectly balanced wave
//  * running-sum fast path (uniform weights, block-wide bitwise vote) with
//    generic 9-tap FMA fallback, as in R4/R5

namespace {
constexpr int KS       = 9;
constexpr int Hh       = 1080;
constexpr int Ww       = 1920;
constexpr int Cc       = 16;
constexpr int OH       = 1072;        // H - 8
constexpr int OW       = 1912;        // W - 8
constexpr int EXT_PX   = 60;          // strip width incl. horizontal halo
constexpr int OUT_PX   = 52;          // output pixels per strip
constexpr int NTH      = EXT_PX * 4;  // 240 threads
constexpr int GRID_X   = 37;          // 37*52 >= 1912, last tile overlapped
constexpr int GRID_Y   = 4;
constexpr int ROWS_PB  = OH / GRID_Y;       // 268 output rows per block
constexpr int ITERS    = ROWS_PB / 4;       // 67 four-row iterations
constexpr int IN_ROWS  = ROWS_PB + 8;       // 276 input rows touched
constexpr int IN_ROW_U2  = Ww * Cc / 4;     // 7680 ulonglong2 per input row
constexpr int OUT_ROW_U2 = OW * Cc / 4;     // 7648 ulonglong2 per output row
constexpr int HTH      = 208;   // horizontal: 4 rows * 13 groups * 4 quads
constexpr int SBN      = 304;   // padded row buffer entries (max idx 295)
}

typedef unsigned long long u64;

__device__ __forceinline__ void fma2(u64 &d, const u64 a, const u64 b) {
    asm("fma.rn.f32x2 %0, %1, %2, %0;" : "+l"(d) : "l"(a), "l"(b));
}
__device__ __forceinline__ void add2(u64 &d, const u64 a) {
    asm("add.rn.f32x2 %0, %0, %1;" : "+l"(d) : "l"(a));
}
__device__ __forceinline__ u64 mul2(const u64 a, const u64 b) {
    u64 r; asm("mul.rn.f32x2 %0, %1, %2;" : "=l"(r) : "l"(a), "l"(b));
    return r;
}
#define NEG1 0xBF800000BF800000ull
__device__ __forceinline__ void sub2(u64 &d, const u64 v) { fma2(d, NEG1, v); }

__device__ __forceinline__ ulonglong2 ldg2(const ulonglong2* p) {
    ulonglong2 v;
    asm volatile("ld.global.v2.u64 {%0,%1}, [%2];"
                 : "=l"(v.x), "=l"(v.y) : "l"(p));
    return v;
}
__device__ __forceinline__ ulonglong2 ldcs2(const ulonglong2* p) {
    ulonglong2 v;
    asm volatile("ld.global.cs.v2.u64 {%0,%1}, [%2];"
                 : "=l"(v.x), "=l"(v.y) : "l"(p));
    return v;
}
__device__ __forceinline__ void stcs2(ulonglong2* p, const u64 a, const u64 b) {
    asm volatile("st.global.cs.v2.u64 [%0], {%1,%2};" :: "l"(p), "l"(a), "l"(b));
}

// padded smem index for pixel p, quad qq (conflict-free per 8-lane phase)
__device__ __forceinline__ int sidx(int p, int qq) {
    return p * 4 + qq + ((p >> 2) << 2);
}

// 9-window sliding sum over 12 taps -> 4 outputs, scaled + streamed out
__device__ __forceinline__ void hphase(const ulonglong2* __restrict__ s,
                                       ulonglong2* __restrict__ ob,
                                       const int hbase, const ulonglong2 scale)
{
    u64 ax0 = 0, ax1 = 0, ax2 = 0, ax3 = 0;
    u64 ay0 = 0, ay1 = 0, ay2 = 0, ay3 = 0;
    #pragma unroll
    for (int j = 0; j < 12; ++j) {
        const ulonglong2 t = s[hbase + j * 4 + ((j >> 2) << 2)];
        if (j < 9)            { add2(ax0, t.x); add2(ay0, t.y); }
        if (j >= 1 && j < 10) { add2(ax1, t.x); add2(ay1, t.y); }
        if (j >= 2 && j < 11) { add2(ax2, t.x); add2(ay2, t.y); }
        if (j >= 3)           { add2(ax3, t.x); add2(ay3, t.y); }
    }
    stcs2(ob + 0,  mul2(scale.x, ax0), mul2(scale.y, ay0));
    stcs2(ob + 4,  mul2(scale.x, ax1), mul2(scale.y, ay1));
    stcs2(ob + 8,  mul2(scale.x, ax2), mul2(scale.y, ay2));
    stcs2(ob + 12, mul2(scale.x, ax3), mul2(scale.y, ay3));
}

__global__ void __launch_bounds__(NTH, 4)
box_kernel(const float* __restrict__ xg, const float* __restrict__ wyg,
           const float* __restrict__ wxg, float* __restrict__ og)
{
    __shared__ ulonglong2 wy_s[KS * 4];
    __shared__ ulonglong2 wx_s[KS * 4];
    __shared__ ulonglong2 sb[2][4][SBN];     // [buf][row-of-quad][padded col]

    const int tid = threadIdx.x;
    const int q   = tid & 3;
    const int pl  = tid >> 2;

    const int bx = blockIdx.x, by = blockIdx.y, b = blockIdx.z;
    const int px0 = min(bx * OUT_PX, OW - OUT_PX);   // overlapped last tile
    const int r0  = by * ROWS_PB;

    const ulonglong2* wyv = reinterpret_cast<const ulonglong2*>(wyg);
    const ulonglong2* wxv = reinterpret_cast<const ulonglong2*>(wxg);
    if (tid < KS * 4)                    wy_s[tid]      = wyv[tid];
    else if (tid >= 64 && tid < 64 + 36) wx_s[tid - 64] = wxv[tid - 64];
    __syncthreads();

    // Block-wide bitwise uniformity vote for this thread's channel quad.
    int myuni = 1;
    {
        const ulonglong2 y0 = wy_s[q], x0 = wx_s[q];
        #pragma unroll
        for (int k = 1; k < KS; ++k) {
            const ulonglong2 yk = wy_s[k * 4 + q], xk = wx_s[k * 4 + q];
            myuni &= (yk.x == y0.x) & (yk.y == y0.y)
                   & (xk.x == x0.x) & (xk.y == x0.y);
        }
    }
    const int uniform = __syncthreads_and(myuni);

    const ulonglong2* ib = reinterpret_cast<const ulonglong2*>(xg)
        + (size_t)(b * Hh + r0) * IN_ROW_U2 + (px0 + pl) * 4 + q;
    const int sst = sidx(pl, q);

    if (uniform) {
        // ------------- fast path: running sums, 4 rows/iter -------------
        const bool hact = (tid < HTH);
        const int  rest = tid >> 2;            // 0..51 when active
        const int  row4 = rest / 13;           // 0..3
        const int  px   = (rest - row4 * 13) * 4;
        const int  hbase = px * 5 + q;

        ulonglong2 scale;
        scale.x = mul2(wy_s[q].x, wx_s[q].x);
        scale.y = mul2(wy_s[q].y, wx_s[q].y);

        ulonglong2* ob = reinterpret_cast<ulonglong2*>(og)
            + (size_t)(b * OH + r0 + row4) * OUT_ROW_U2 + (px0 + px) * 4 + q;

        // Prologue: S = sum rows 0..8; keep rows 0..3 as first leaving rows.
        u64 Sx, Sy;
        ulonglong2 Lo0, Lo1, Lo2, Lo3;
        {
            Lo0 = ldg2(ib);
            Sx = Lo0.x; Sy = Lo0.y;
            Lo1 = ldg2(ib + 1 * IN_ROW_U2); add2(Sx, Lo1.x); add2(Sy, Lo1.y);
            Lo2 = ldg2(ib + 2 * IN_ROW_U2); add2(Sx, Lo2.x); add2(Sy, Lo2.y);
            Lo3 = ldg2(ib + 3 * IN_ROW_U2); add2(Sx, Lo3.x); add2(Sy, Lo3.y);
            #pragma unroll
            for (int k = 4; k < 9; ++k) {
                const ulonglong2 v = ldg2(ib + k * IN_ROW_U2);
                add2(Sx, v.x); add2(Sy, v.y);
            }
        }

        // Iteration 0 (peeled): rows 0..3
        {
            ulonglong2 Ln0 = ldg2(ib +  9 * IN_ROW_U2);
            ulonglong2 Ln1 = ldg2(ib + 10 * IN_ROW_U2);
            ulonglong2 Ln2 = ldg2(ib + 11 * IN_ROW_U2);
            ulonglong2 Ln3 = ldg2(ib + 12 * IN_ROW_U2);

            { ulonglong2 v; v.x = Sx; v.y = Sy; sb[0][0][sst] = v; }
            add2(Sx, Ln0.x); sub2(Sx, Lo0.x); add2(Sy, Ln0.y); sub2(Sy, Lo0.y);
            { ulonglong2 v; v.x = Sx; v.y = Sy; sb[0][1][sst] = v; }
            add2(Sx, Ln1.x); sub2(Sx, Lo1.x); add2(Sy, Ln1.y); sub2(Sy, Lo1.y);
            { ulonglong2 v; v.x = Sx; v.y = Sy; sb[0][2][sst] = v; }
            add2(Sx, Ln2.x); sub2(Sx, Lo2.x); add2(Sy, Ln2.y); sub2(Sy, Lo2.y);
            { ulonglong2 v; v.x = Sx; v.y = Sy; sb[0][3][sst] = v; }
            add2(Sx, Ln3.x); sub2(Sx, Lo3.x); add2(Sy, Ln3.y); sub2(Sy, Lo3.y);
            __syncthreads();
        }

        for (int i = 1; i < ITERS; ++i) {
            const int r = 4 * i;
            // 1) issue all 8 loads for iter i
            Lo0 = ldcs2(ib + (r + 0) * IN_ROW_U2);
            Lo1 = ldcs2(ib + (r + 1) * IN_ROW_U2);
            Lo2 = ldcs2(ib + (r + 2) * IN_ROW_U2);
            Lo3 = ldcs2(ib + (r + 3) * IN_ROW_U2);
            ulonglong2 Ln0 = ldg2(ib + (r +  9) * IN_ROW_U2);
            ulonglong2 Ln1 = ldg2(ib + (r + 10) * IN_ROW_U2);
            ulonglong2 Ln2 = ldg2(ib + (r + 11) * IN_ROW_U2);
            ulonglong2 Ln3 = ldg2(ib + min(r + 12, IN_ROWS - 1) * IN_ROW_U2);

            // 2) horizontal for iter i-1 (covers the load latency)
            if (hact) {
                hphase(sb[(i - 1) & 1][row4], ob, hbase, scale);
                ob += 4 * OUT_ROW_U2;
            }

            // 3) vertical advance: rows r..r+3 into sb[i&1]
            const int buf = i & 1;
            { ulonglong2 v; v.x = Sx; v.y = Sy; sb[buf][0][sst] = v; }
            add2(Sx, Ln0.x); sub2(Sx, Lo0.x); add2(Sy, Ln0.y); sub2(Sy, Lo0.y);
            { ulonglong2 v; v.x = Sx; v.y = Sy; sb[buf][1][sst] = v; }
            add2(Sx, Ln1.x); sub2(Sx, Lo1.x); add2(Sy, Ln1.y); sub2(Sy, Lo1.y);
            { ulonglong2 v; v.x = Sx; v.y = Sy; sb[buf][2][sst] = v; }
            add2(Sx, Ln2.x); sub2(Sx, Lo2.x); add2(Sy, Ln2.y); sub2(Sy, Lo2.y);
            { ulonglong2 v; v.x = Sx; v.y = Sy; sb[buf][3][sst] = v; }
            add2(Sx, Ln3.x); sub2(Sx, Lo3.x); add2(Sy, Ln3.y); sub2(Sy, Lo3.y);

            __syncthreads();
        }

        // Epilogue: horizontal for the last iteration (buf (ITERS-1)&1 = 0).
        if (hact)
            hphase(sb[(ITERS - 1) & 1][row4], ob, hbase, scale);
    } else {
        // ------------- fallback: full 9-tap FMA (any weights) -------------
        const bool emit = (pl < OUT_PX);
        ulonglong2* op = reinterpret_cast<ulonglong2*>(og)
            + (size_t)(b * OH + r0) * OUT_ROW_U2 + (px0 + pl) * 4 + q;

        ulonglong2 win[8], cur, nxt;
        const ulonglong2* ip = ib;
        #pragma unroll
        for (int k = 0; k < 8; ++k) { win[k] = *ip; ip += IN_ROW_U2; }
        cur = *ip; ip += IN_ROW_U2;
        nxt = *ip; ip += IN_ROW_U2;

        for (int i = 0; i < ROWS_PB / 2; ++i) {
            ulonglong2 p0 = cur, p1 = cur;
            if (2 * i + 10 < IN_ROWS) p0 = ip[0];
            if (2 * i + 11 < IN_ROWS) p1 = ip[IN_ROW_U2];
            ip += 2 * IN_ROW_U2;

            u64 a0x = 0, a0y = 0, a1x = 0, a1y = 0;
            #pragma unroll
            for (int k = 0; k < KS; ++k) {
                const ulonglong2 w   = wy_s[k * 4 + q];
                const ulonglong2 r0v = (k < 8) ? win[k] : cur;
                const ulonglong2 r1v = (k < 7) ? win[k + 1] : ((k == 7) ? cur : nxt);
                fma2(a0x, w.x, r0v.x); fma2(a0y, w.y, r0v.y);
                fma2(a1x, w.x, r1v.x); fma2(a1y, w.y, r1v.y);
            }
            const int buf = i & 1;
            { ulonglong2 v; v.x = a0x; v.y = a0y; sb[buf][0][sst] = v; }
            { ulonglong2 v; v.x = a1x; v.y = a1y; sb[buf][1][sst] = v; }

            #pragma unroll
            for (int k = 0; k < 6; ++k) win[k] = win[k + 2];
            win[6] = cur; win[7] = nxt;
            cur = p0; nxt = p1;

            __syncthreads();

            if (emit) {
                u64 o0x = 0, o0y = 0, o1x = 0, o1y = 0;
                #pragma unroll
                for (int j = 0; j < KS; ++j) {
                    const ulonglong2 w  = wx_s[j * 4 + q];
                    const ulonglong2 t0 = sb[buf][0][sidx(pl + j, q)];
                    const ulonglong2 t1 = sb[buf][1][sidx(pl + j, q)];
                    fma2(o0x, w.x, t0.x); fma2(o0y, w.y, t0.y);
                    fma2(o1x, w.x, t1.x); fma2(o1y, w.y, t1.y);
                }
                ulonglong2 v0; v0.x = o0x; v0.y = o0y;
                ulonglong2 v1; v1.x = o1x; v1.y = o1y;
                op[0]          = v0;
                op[OUT_ROW_U2] = v1;
            }
            op += 2 * OUT_ROW_U2;
            __syncthreads();
        }
    }
}

extern "C" void kernel_launch(void* const* d_in, const int* in_sizes, int n_in,
                              void* d_out, int out_size)
{
    const float* x  = (const float*)d_in[0];
    const float* wy = (const float*)d_in[1];
    const float* wx = (const float*)d_in[2];
    float* out = (float*)d_out;

    dim3 grid(GRID_X, GRID_Y, 4);
    dim3 block(NTH);
    box_kernel<<<grid, block>>>(x, wy, wx, out);
}

// round 7
// speedup vs baseline: 2.0304x; 1.0950x over previous
#include <cuda_runtime.h>

// BoxFilter fused separable 9x9 depthwise conv, fp32 NHWC.
// B=4, H=1080, W=1920, C=16 -> out [4, 1072, 1912, 16].
//
// Round-7: R6 was co-limited by L1 (77%) and DRAM (66%); taps were 40% of L1
// wavefronts at 3 LDS per output. Changes:
//  * horizontal pass: 8 outputs per thread via sliding 9-window sum
//    (16 taps / 8 outputs = 2.0 LDS per output)
//  * horizontal granularity u64 (2 channels): halves tap register footprint
//    so the sliding form fits 64 regs; warps 0..6 fully active, warp 7 idle
//  * EXT=64/OUT=56/256 threads, grid (35,4,4) = 560 blocks, 4 blocks/SM
//  * padded smem (+4 slots per 8-px group) + SBN=300: conflict-free taps,
//    including the two cross-row boundary phases
//  * DRAM-critical new-row loads issued before the horizontal phase; L2
//    re-reads of leaving rows issued after it (register cap)

namespace {
constexpr int KS       = 9;
constexpr int Hh       = 1080;
constexpr int Ww       = 1920;
constexpr int Cc       = 16;
constexpr int OH       = 1072;        // H - 8
constexpr int OW       = 1912;        // W - 8
constexpr int EXT_PX   = 64;          // strip width incl. horizontal halo
constexpr int OUT_PX   = 56;          // output pixels per strip
constexpr int NTH      = 256;
constexpr int GRID_X   = 35;          // 35*56 >= 1912, last tile overlapped
constexpr int GRID_Y   = 4;
constexpr int ROWS_PB  = OH / GRID_Y;       // 268 output rows per block
constexpr int ITERS    = ROWS_PB / 4;       // 67 four-row iterations
constexpr int IN_ROWS  = ROWS_PB + 8;       // 276 input rows touched
constexpr int IN_ROW_U2   = Ww * Cc / 4;    // 7680 ulonglong2 per input row
constexpr int OUT_ROW_U2  = OW * Cc / 4;    // 7648 ulonglong2 per output row
constexpr int OUT_ROW_U64 = OW * Cc / 2;    // 15296 u64 per output row
constexpr int HTH      = 224;   // 4 rows * 7 groups * 8 half-quads
constexpr int SBN      = 300;   // padded entries; 300 % 8 == 4 (boundary ok)
}

typedef unsigned long long u64;

__device__ __forceinline__ void fma2(u64 &d, const u64 a, const u64 b) {
    asm("fma.rn.f32x2 %0, %1, %2, %0;" : "+l"(d) : "l"(a), "l"(b));
}
__device__ __forceinline__ void add2(u64 &d, const u64 a) {
    asm("add.rn.f32x2 %0, %0, %1;" : "+l"(d) : "l"(a));
}
__device__ __forceinline__ u64 mul2(const u64 a, const u64 b) {
    u64 r; asm("mul.rn.f32x2 %0, %1, %2;" : "=l"(r) : "l"(a), "l"(b));
    return r;
}
#define NEG1 0xBF800000BF800000ull
__device__ __forceinline__ void sub2(u64 &d, const u64 v) { fma2(d, NEG1, v); }

__device__ __forceinline__ ulonglong2 ldg2(const ulonglong2* p) {
    ulonglong2 v;
    asm volatile("ld.global.v2.u64 {%0,%1}, [%2];"
                 : "=l"(v.x), "=l"(v.y) : "l"(p));
    return v;
}
__device__ __forceinline__ ulonglong2 ldcs2(const ulonglong2* p) {
    ulonglong2 v;
    asm volatile("ld.global.cs.v2.u64 {%0,%1}, [%2];"
                 : "=l"(v.x), "=l"(v.y) : "l"(p));
    return v;
}
__device__ __forceinline__ void stcs1(u64* p, const u64 a) {
    asm volatile("st.global.cs.u64 [%0], %1;" :: "l"(p), "l"(a));
}

// padded smem index (ulonglong2 units) for pixel p, quad qq:
// +4 slots per 8-pixel group
__device__ __forceinline__ int sidx(int p, int qq) {
    return p * 4 + qq + ((p >> 3) << 2);
}

// Horizontal: 8 outputs from 16 taps via sliding 9-window sum (u64 lanes).
__device__ __forceinline__ void hphase8(const u64* __restrict__ s,
                                        u64* __restrict__ ob,
                                        const int hbase, const u64 scale)
{
    u64 t[16];
    #pragma unroll
    for (int j = 0; j < 16; ++j)
        t[j] = s[hbase + j * 8 + ((j >> 3) << 3)];

    u64 acc = t[0];
    #pragma unroll
    for (int j = 1; j < 9; ++j) add2(acc, t[j]);
    stcs1(ob, mul2(scale, acc));
    #pragma unroll
    for (int o = 1; o < 8; ++o) {
        add2(acc, t[o + 8]);
        sub2(acc, t[o - 1]);
        stcs1(ob + o * 8, mul2(scale, acc));
    }
}

__global__ void __launch_bounds__(NTH, 4)
box_kernel(const float* __restrict__ xg, const float* __restrict__ wyg,
           const float* __restrict__ wxg, float* __restrict__ og)
{
    __shared__ ulonglong2 wy_s[KS * 4];
    __shared__ ulonglong2 wx_s[KS * 4];
    __shared__ ulonglong2 sb[2][4][SBN];     // [buf][row-of-quad][padded col]

    const int tid = threadIdx.x;
    const int q   = tid & 3;
    const int pl  = tid >> 2;                // 0..63 (vertical pixel)

    const int bx = blockIdx.x, by = blockIdx.y, bz = blockIdx.z;
    const int px0 = min(bx * OUT_PX, OW - OUT_PX);   // overlapped last tile
    const int r0  = by * ROWS_PB;

    const ulonglong2* wyv = reinterpret_cast<const ulonglong2*>(wyg);
    const ulonglong2* wxv = reinterpret_cast<const ulonglong2*>(wxg);
    if (tid < KS * 4)                    wy_s[tid]      = wyv[tid];
    else if (tid >= 64 && tid < 64 + 36) wx_s[tid - 64] = wxv[tid - 64];
    __syncthreads();

    // Block-wide bitwise uniformity vote for this thread's channel quad.
    int myuni = 1;
    {
        const ulonglong2 y0 = wy_s[q], x0 = wx_s[q];
        #pragma unroll
        for (int k = 1; k < KS; ++k) {
            const ulonglong2 yk = wy_s[k * 4 + q], xk = wx_s[k * 4 + q];
            myuni &= (yk.x == y0.x) & (yk.y == y0.y)
                   & (xk.x == x0.x) & (xk.y == x0.y);
        }
    }
    const int uniform = __syncthreads_and(myuni);

    const ulonglong2* ib = reinterpret_cast<const ulonglong2*>(xg)
        + (size_t)(bz * Hh + r0) * IN_ROW_U2 + (px0 + pl) * 4 + q;
    const int sst = sidx(pl, q);

    if (uniform) {
        // ------------- fast path: running sums, 4 rows/iter -------------
        const bool hact  = (tid < HTH);      // warps 0..6
        const int  hq    = tid & 7;          // u64 lane within pixel
        const int  hrest = tid >> 3;         // 0..27 when active
        const int  row4  = hrest / 7;
        const int  gx    = hrest - row4 * 7; // 8-px group
        const int  hbase = 72 * gx + hq;

        u64 scale;
        {
            const ulonglong2 wyq = wy_s[hq >> 1];
            const ulonglong2 wxq = wx_s[hq >> 1];
            const u64 a = (hq & 1) ? wyq.y : wyq.x;
            const u64 c = (hq & 1) ? wxq.y : wxq.x;
            scale = mul2(a, c);
        }

        u64* ob = reinterpret_cast<u64*>(og)
            + (size_t)(bz * OH + r0 + row4) * OUT_ROW_U64
            + (size_t)(px0 + gx * 8) * 8 + hq;

        // Prologue: S = sum rows 0..8; keep rows 0..3 as first leaving rows.
        u64 Sx, Sy;
        ulonglong2 Lo0, Lo1, Lo2, Lo3;
        {
            Lo0 = ldg2(ib);
            Sx = Lo0.x; Sy = Lo0.y;
            Lo1 = ldg2(ib + 1 * IN_ROW_U2); add2(Sx, Lo1.x); add2(Sy, Lo1.y);
            Lo2 = ldg2(ib + 2 * IN_ROW_U2); add2(Sx, Lo2.x); add2(Sy, Lo2.y);
            Lo3 = ldg2(ib + 3 * IN_ROW_U2); add2(Sx, Lo3.x); add2(Sy, Lo3.y);
            #pragma unroll
            for (int k = 4; k < 9; ++k) {
                const ulonglong2 v = ldg2(ib + k * IN_ROW_U2);
                add2(Sx, v.x); add2(Sy, v.y);
            }
        }

        // Iteration 0 (peeled): rows 0..3
        {
            ulonglong2 Ln0 = ldg2(ib +  9 * IN_ROW_U2);
            ulonglong2 Ln1 = ldg2(ib + 10 * IN_ROW_U2);
            ulonglong2 Ln2 = ldg2(ib + 11 * IN_ROW_U2);
            ulonglong2 Ln3 = ldg2(ib + 12 * IN_ROW_U2);

            { ulonglong2 v; v.x = Sx; v.y = Sy; sb[0][0][sst] = v; }
            add2(Sx, Ln0.x); sub2(Sx, Lo0.x); add2(Sy, Ln0.y); sub2(Sy, Lo0.y);
            { ulonglong2 v; v.x = Sx; v.y = Sy; sb[0][1][sst] = v; }
            add2(Sx, Ln1.x); sub2(Sx, Lo1.x); add2(Sy, Ln1.y); sub2(Sy, Lo1.y);
            { ulonglong2 v; v.x = Sx; v.y = Sy; sb[0][2][sst] = v; }
            add2(Sx, Ln2.x); sub2(Sx, Lo2.x); add2(Sy, Ln2.y); sub2(Sy, Lo2.y);
            { ulonglong2 v; v.x = Sx; v.y = Sy; sb[0][3][sst] = v; }
            add2(Sx, Ln3.x); sub2(Sx, Lo3.x); add2(Sy, Ln3.y); sub2(Sy, Lo3.y);
            __syncthreads();
        }

        for (int i = 1; i < ITERS; ++i) {
            const int r = 4 * i;
            // 1) DRAM-critical new-row loads first
            ulonglong2 Ln0 = ldg2(ib + (r +  9) * IN_ROW_U2);
            ulonglong2 Ln1 = ldg2(ib + (r + 10) * IN_ROW_U2);
            ulonglong2 Ln2 = ldg2(ib + (r + 11) * IN_ROW_U2);
            ulonglong2 Ln3 = ldg2(ib + min(r + 12, IN_ROWS - 1) * IN_ROW_U2);

            // 2) horizontal for iter i-1 (covers load latency)
            if (hact) {
                hphase8(reinterpret_cast<const u64*>(sb[(i - 1) & 1][row4]),
                        ob, hbase, scale);
                ob += 4 * OUT_ROW_U64;
            }

            // 3) leaving-row reloads (L2 hits)
            Lo0 = ldcs2(ib + (r + 0) * IN_ROW_U2);
            Lo1 = ldcs2(ib + (r + 1) * IN_ROW_U2);
            Lo2 = ldcs2(ib + (r + 2) * IN_ROW_U2);
            Lo3 = ldcs2(ib + (r + 3) * IN_ROW_U2);

            // 4) vertical advance: rows r..r+3 into sb[i&1]
            const int buf = i & 1;
            { ulonglong2 v; v.x = Sx; v.y = Sy; sb[buf][0][sst] = v; }
            add2(Sx, Ln0.x); sub2(Sx, Lo0.x); add2(Sy, Ln0.y); sub2(Sy, Lo0.y);
            { ulonglong2 v; v.x = Sx; v.y = Sy; sb[buf][1][sst] = v; }
            add2(Sx, Ln1.x); sub2(Sx, Lo1.x); add2(Sy, Ln1.y); sub2(Sy, Lo1.y);
            { ulonglong2 v; v.x = Sx; v.y = Sy; sb[buf][2][sst] = v; }
            add2(Sx, Ln2.x); sub2(Sx, Lo2.x); add2(Sy, Ln2.y); sub2(Sy, Lo2.y);
            { ulonglong2 v; v.x = Sx; v.y = Sy; sb[buf][3][sst] = v; }
            add2(Sx, Ln3.x); sub2(Sx, Lo3.x); add2(Sy, Ln3.y); sub2(Sy, Lo3.y);

            __syncthreads();
        }

        // Epilogue: horizontal for the last iteration.
        if (hact)
            hphase8(reinterpret_cast<const u64*>(sb[(ITERS - 1) & 1][row4]),
                    ob, hbase, scale);
    } else {
        // ------------- fallback: full 9-tap FMA (any weights) -------------
        const bool emit = (pl < OUT_PX);
        ulonglong2* op = reinterpret_cast<ulonglong2*>(og)
            + (size_t)(bz * OH + r0) * OUT_ROW_U2 + (px0 + pl) * 4 + q;

        ulonglong2 win[8], cur, nxt;
        const ulonglong2* ip = ib;
        #pragma unroll
        for (int k = 0; k < 8; ++k) { win[k] = *ip; ip += IN_ROW_U2; }
        cur = *ip; ip += IN_ROW_U2;
        nxt = *ip; ip += IN_ROW_U2;

        for (int i = 0; i < ROWS_PB / 2; ++i) {
            ulonglong2 p0 = cur, p1 = cur;
            if (2 * i + 10 < IN_ROWS) p0 = ip[0];
            if (2 * i + 11 < IN_ROWS) p1 = ip[IN_ROW_U2];
            ip += 2 * IN_ROW_U2;

            u64 a0x = 0, a0y = 0, a1x = 0, a1y = 0;
            #pragma unroll
            for (int k = 0; k < KS; ++k) {
                const ulonglong2 w   = wy_s[k * 4 + q];
                const ulonglong2 r0v = (k < 8) ? win[k] : cur;
                const ulonglong2 r1v = (k < 7) ? win[k + 1] : ((k == 7) ? cur : nxt);
                fma2(a0x, w.x, r0v.x); fma2(a0y, w.y, r0v.y);
                fma2(a1x, w.x, r1v.x); fma2(a1y, w.y, r1v.y);
            }
            const int buf = i & 1;
            { ulonglong2 v; v.x = a0x; v.y = a0y; sb[buf][0][sst] = v; }
            { ulonglong2 v; v.x = a1x; v.y = a1y; sb[buf][1][sst] = v; }

            #pragma unroll
            for (int k = 0; k < 6; ++k) win[k] = win[k + 2];
            win[6] = cur; win[7] = nxt;
            cur = p0; nxt = p1;

            __syncthreads();

            if (emit) {
                u64 o0x = 0, o0y = 0, o1x = 0, o1y = 0;
                #pragma unroll
                for (int j = 0; j < KS; ++j) {
                    const ulonglong2 w  = wx_s[j * 4 + q];
                    const ulonglong2 t0 = sb[buf][0][sidx(pl + j, q)];
                    const ulonglong2 t1 = sb[buf][1][sidx(pl + j, q)];
                    fma2(o0x, w.x, t0.x); fma2(o0y, w.y, t0.y);
                    fma2(o1x, w.x, t1.x); fma2(o1y, w.y, t1.y);
                }
                ulonglong2 v0; v0.x = o0x; v0.y = o0y;
                ulonglong2 v1; v1.x = o1x; v1.y = o1y;
                op[0]          = v0;
                op[OUT_ROW_U2] = v1;
            }
            op += 2 * OUT_ROW_U2;
            __syncthreads();
        }
    }
}

extern "C" void kernel_launch(void* const* d_in, const int* in_sizes, int n_in,
                              void* d_out, int out_size)
{
    const float* x  = (const float*)d_in[0];
    const float* wy = (const float*)d_in[1];
    const float* wx = (const float*)d_in[2];
    float* out = (float*)d_out;

    dim3 grid(GRID_X, GRID_Y, 4);
    dim3 block(NTH);
    box_kernel<<<grid, block>>>(x, wy, wx, out);
}